// round 9
// baseline (speedup 1.0000x reference)
#include <cuda_runtime.h>
#include <cstdint>

#define BATCH  4
#define CH     192
#define NPTS   3136
#define KNN    9
#define NSPLIT 3
#define NTILES 49            /* m-tiles / n-tiles of 64 */
#define RP_ELEMS (NPTS * NPTS)
#define POS_INF __int_as_float(0x7f800000)

#define NBLKS 196            /* NPTS/16  (A m16 blocks)  */
#define MBLKS 392            /* NPTS/8   (B n8  blocks)  */
#define KSTEPS 24            /* CH/8 */

// ---------------- scratch (device globals; no allocation allowed) ----------
// gA: A-operand fragments: [b][nblk][ks][split][lane][reg]  (float)
__device__ __align__(16) float g_xA[(size_t)BATCH * NBLKS * KSTEPS * 2 * 32 * 4];
// gB: B-operand fragments: [b][mblk][ks][lane][w]  w={b0s0,b1s0,b0s1,b1s1}
__device__ __align__(16) float g_yB[(size_t)BATCH * MBLKS * KSTEPS * 32 * 4];
__device__ float g_xn2[BATCH * NPTS];
__device__ float g_yn2[BATCH * NPTS];
__device__ float g_pv[BATCH * NPTS * NSPLIT * KNN];
__device__ int   g_pi[BATCH * NPTS * NSPLIT * KNN];

__device__ __forceinline__ bool lex_less(float v, int i, float v2, int i2) {
    return (v < v2) || (v == v2 && i < i2);
}
#define TOPK_INSERT(v, idx, LV, LI)                                        \
  do {                                                                     \
    if (lex_less((v), (idx), LV[KNN-1], LI[KNN-1])) {                      \
      LV[KNN-1] = (v); LI[KNN-1] = (idx);                                  \
      _Pragma("unroll")                                                    \
      for (int _j = KNN-1; _j > 0; --_j) {                                 \
        if (lex_less(LV[_j], LI[_j], LV[_j-1], LI[_j-1])) {                \
          float _tv = LV[_j]; LV[_j] = LV[_j-1]; LV[_j-1] = _tv;           \
          int   _ti = LI[_j]; LI[_j] = LI[_j-1]; LI[_j-1] = _ti;           \
        }                                                                  \
      }                                                                    \
    }                                                                      \
  } while (0)

#define CVT_TF32(u, f) asm("cvt.rna.tf32.f32 %0, %1;" : "=r"(u) : "f"(f))

#define MMA_TF32(d, a, bb0, bb1)                                           \
  asm volatile("mma.sync.aligned.m16n8k8.row.col.f32.tf32.tf32.f32 "       \
      "{%0,%1,%2,%3},{%4,%5,%6,%7},{%8,%9},{%0,%1,%2,%3};"                 \
      : "+f"((d)[0]), "+f"((d)[1]), "+f"((d)[2]), "+f"((d)[3])             \
      : "r"((a).x), "r"((a).y), "r"((a).z), "r"((a).w),                    \
        "r"(bb0), "r"(bb1))

// ------ kernel 1: L2-normalize over C + tf32 split + fragment scatter ------
__global__ void normalize_split(const float* __restrict__ xin,
                                const float* __restrict__ yin) {
    int sel = blockIdx.z;                     // 0: x -> gA, 1: y -> gB
    const float* src = sel ? yin : xin;
    float* s2o = sel ? g_yn2 : g_xn2;
    int b  = blockIdx.y;
    int n0 = blockIdx.x * 32;
    int tx = threadIdx.x, ty = threadIdx.y;   // 32 x 8
    int tid = ty * 32 + tx;

    __shared__ float tile[CH][33];
    __shared__ float red[8][33];
    __shared__ float dnm[32];

    const float* sb = src + (size_t)b * CH * NPTS + n0 + tx;
    float acc = 0.f;
    #pragma unroll
    for (int c = ty; c < CH; c += 8) {
        float v = sb[(size_t)c * NPTS];
        tile[c][tx] = v;
        acc += v * v;
    }
    red[ty][tx] = acc;
    __syncthreads();
    if (ty == 0) {
        float s = red[0][tx];
        #pragma unroll
        for (int j = 1; j < 8; j++) s += red[j][tx];
        dnm[tx] = fmaxf(sqrtf(s), 1e-12f);
    }
    __syncthreads();

    // write phase: thread -> (row r, 24-channel chunk)
    int r  = tid >> 3;
    int cb = (tid & 7) * 24;
    float dn = dnm[r];
    int n = n0 + r;
    float s2 = 0.f;
    #pragma unroll
    for (int k = 0; k < 24; k++) {
        int c = cb + k;
        float v = tile[c][r] / dn;
        s2 += v * v;
        uint32_t u0; CVT_TF32(u0, v);
        float v0 = __uint_as_float(u0);
        uint32_t u1; CVT_TF32(u1, v - v0);

        int lane = ((n & 7) << 2) | (c & 3);
        int ks   = c >> 3;
        if (sel == 0) {
            int reg = ((n >> 3) & 1) | (((c >> 2) & 1) << 1);
            size_t base = ((((size_t)b * NBLKS + (n >> 4)) * KSTEPS + ks) * 2);
            g_xA[((base + 0) * 32 + lane) * 4 + reg] = __uint_as_float(u0);
            g_xA[((base + 1) * 32 + lane) * 4 + reg] = __uint_as_float(u1);
        } else {
            int whalf = (c >> 2) & 1;
            size_t base = ((((size_t)b * MBLKS + (n >> 3)) * KSTEPS + ks) * 32 + lane) * 4;
            g_yB[base + whalf]     = __uint_as_float(u0);
            g_yB[base + 2 + whalf] = __uint_as_float(u1);
        }
    }
    #pragma unroll
    for (int o = 4; o > 0; o >>= 1)
        s2 += __shfl_down_sync(0xffffffffu, s2, o, 8);
    if ((tid & 7) == 0) s2o[(size_t)b * NPTS + n] = s2;
}

// ------- kernel 2: 3xTF32 mma.sync GEMM 64x64 tiles + streaming top-9 ------
__global__ void __launch_bounds__(128, 4)
knn_mma(const float* __restrict__ rp) {
    __shared__ union {
        float bstage[2][2048];              // 2 x 8 KB B-fragment buffers
        struct { float cv[64 * 18]; int ci[64 * 18]; } c;
    } shr;
    __shared__ float ds[64 * 65];           // raw dot products
    __shared__ float x2s[64], y2sh[64];

    int b     = blockIdx.z;
    int split = blockIdx.y;
    int nt    = blockIdx.x;
    int n0    = nt * 64;

    int tid  = threadIdx.x;
    int lane = tid & 31;
    int wid  = tid >> 5;
    int wn   = wid & 1;          // n half (rows wn*32)
    int wm   = wid >> 1;         // m half (cols wm*32)
    int srow = tid & 63, half = tid >> 6;   // scan role

    if (tid < 64) x2s[tid] = g_xn2[b * NPTS + n0 + tid];

    float bvK[KNN]; int biK[KNN];
    #pragma unroll
    for (int j = 0; j < KNN; j++) { bvK[j] = POS_INF; biK[j] = 0x7FFFFFFF; }

    int t_lo = (split == 0) ? 0  : (split == 1 ? 17 : 33);
    int t_hi = (split == 0) ? 17 : (split == 1 ? 33 : 49);

    const uint4*  gA4 = (const uint4*)g_xA;
    const float4* gB4 = (const float4*)g_yB;
    size_t nb0 = (size_t)b * NBLKS + nt * 4 + wn * 2;   // warp's first nblk

    for (int mt = t_lo; mt < t_hi; mt++) {
        int m0 = mt * 64;
        float acc[2][4][4];
        #pragma unroll
        for (int bi = 0; bi < 2; bi++)
            #pragma unroll
            for (int bj = 0; bj < 4; bj++)
                #pragma unroll
                for (int e = 0; e < 4; e++) acc[bi][bj][e] = 0.f;

        const float4* gsrcb = gB4 + ((size_t)b * MBLKS + mt * 8) * 768;

        // stage chunk 0 into buffer 0
        #pragma unroll
        for (int i = 0; i < 4; i++) {
            int f = tid + i * 128;
            ((float4*)shr.bstage[0])[f] = gsrcb[(f >> 6) * 768 + (f & 63)];
        }
        if (tid < 64) y2sh[tid] = g_yn2[b * NPTS + m0 + tid];
        __syncthreads();

        int buf = 0;
        for (int kc = 0; kc < 12; kc++) {
            // prefetch next chunk into registers
            float4 pf[4];
            bool hn = (kc < 11);
            if (hn) {
                const float4* gs = gsrcb + (kc + 1) * 64;
                #pragma unroll
                for (int i = 0; i < 4; i++) {
                    int f = tid + i * 128;
                    pf[i] = gs[(f >> 6) * 768 + (f & 63)];
                }
            }

            // compute on current buffer
            #pragma unroll
            for (int kl = 0; kl < 2; kl++) {
                int ks = kc * 2 + kl;
                uint4 afr[2][2];
                #pragma unroll
                for (int bi = 0; bi < 2; bi++)
                    #pragma unroll
                    for (int s = 0; s < 2; s++)
                        afr[bi][s] = gA4[(((nb0 + bi) * KSTEPS + ks) * 2 + s) * 32 + lane];
                uint4 bfr[4];
                #pragma unroll
                for (int bj = 0; bj < 4; bj++)
                    bfr[bj] = ((const uint4*)shr.bstage[buf])
                                  [((wm * 4 + bj) * 2 + kl) * 32 + lane];
                // term 1: x0*y0
                #pragma unroll
                for (int bi = 0; bi < 2; bi++)
                    #pragma unroll
                    for (int bj = 0; bj < 4; bj++)
                        MMA_TF32(acc[bi][bj], afr[bi][0], bfr[bj].x, bfr[bj].y);
                // term 2: x0*y1
                #pragma unroll
                for (int bi = 0; bi < 2; bi++)
                    #pragma unroll
                    for (int bj = 0; bj < 4; bj++)
                        MMA_TF32(acc[bi][bj], afr[bi][0], bfr[bj].z, bfr[bj].w);
                // term 3: x1*y0
                #pragma unroll
                for (int bi = 0; bi < 2; bi++)
                    #pragma unroll
                    for (int bj = 0; bj < 4; bj++)
                        MMA_TF32(acc[bi][bj], afr[bi][1], bfr[bj].x, bfr[bj].y);
            }

            // store prefetched chunk into the other buffer
            if (hn) {
                #pragma unroll
                for (int i = 0; i < 4; i++)
                    ((float4*)shr.bstage[buf ^ 1])[tid + i * 128] = pf[i];
            }
            __syncthreads();
            buf ^= 1;
        }

        // epilogue: scatter raw dot products to ds (SCALAR stores — row
        // stride 65 is odd, so float2 stores would be 4B-misaligned)
        #pragma unroll
        for (int bi = 0; bi < 2; bi++)
            #pragma unroll
            for (int bj = 0; bj < 4; bj++) {
                int r0 = wn * 32 + bi * 16 + (lane >> 2);
                int c0 = wm * 32 + bj * 8 + (lane & 3) * 2;
                ds[r0 * 65 + c0]           = acc[bi][bj][0];
                ds[r0 * 65 + c0 + 1]       = acc[bi][bj][1];
                ds[(r0 + 8) * 65 + c0]     = acc[bi][bj][2];
                ds[(r0 + 8) * 65 + c0 + 1] = acc[bi][bj][3];
            }
        __syncthreads();

        // scan: 2 threads per row, 32 cols each, streaming top-9
        {
            float x2v = x2s[srow];
            const float*  dsr = ds + srow * 65 + half * 32;
            const float4* rpr = (const float4*)(rp + (size_t)(n0 + srow) * NPTS
                                                + m0 + half * 32);
            #pragma unroll
            for (int c4 = 0; c4 < 8; c4++) {
                float4 rv = rpr[c4];
                float rr[4] = {rv.x, rv.y, rv.z, rv.w};
                #pragma unroll
                for (int e = 0; e < 4; e++) {
                    int c  = c4 * 4 + e;
                    float xy = dsr[c];
                    float d2 = x2v + y2sh[half * 32 + c] - 2.0f * xy;
                    float d  = sqrtf(fmaxf(d2, 0.0f)) + rr[e];
                    TOPK_INSERT(d, m0 + half * 32 + c, bvK, biK);
                }
            }
        }
        __syncthreads();   // scan done before next m-tile overwrites smem
    }

    // dump per-thread candidates (aliases dead B buffers) and merge halves
    #pragma unroll
    for (int j = 0; j < KNN; j++) {
        shr.c.cv[srow * 18 + half * 9 + j] = bvK[j];
        shr.c.ci[srow * 18 + half * 9 + j] = biK[j];
    }
    __syncthreads();
    if (tid < 64) {
        float mv[KNN]; int mi[KNN];
        #pragma unroll
        for (int j = 0; j < KNN; j++) { mv[j] = POS_INF; mi[j] = 0x7FFFFFFF; }
        #pragma unroll
        for (int t = 0; t < 18; t++) {
            float v = shr.c.cv[tid * 18 + t]; int ii = shr.c.ci[tid * 18 + t];
            TOPK_INSERT(v, ii, mv, mi);
        }
        size_t base = ((size_t)(b * NPTS + n0 + tid) * NSPLIT + split) * KNN;
        #pragma unroll
        for (int j = 0; j < KNN; j++) { g_pv[base + j] = mv[j]; g_pi[base + j] = mi[j]; }
    }
}

// --------- kernel 3: merge splits, emit (2,B,N,K) as FLOAT32 --------------
__global__ void knn_finalize(float* __restrict__ out) {
    int gid = blockIdx.x * blockDim.x + threadIdx.x;  // b*NPTS + n
    if (gid >= BATCH * NPTS) return;
    float mv[KNN]; int mi[KNN];
    #pragma unroll
    for (int j = 0; j < KNN; j++) { mv[j] = POS_INF; mi[j] = 0x7FFFFFFF; }
    size_t base = (size_t)gid * NSPLIT * KNN;
    for (int t = 0; t < NSPLIT * KNN; t++) {
        float v = g_pv[base + t]; int ii = g_pi[base + t];
        TOPK_INSERT(v, ii, mv, mi);
    }
    int n = gid % NPTS;
    float* o0 = out + (size_t)gid * KNN;                              // nn_idx
    float* o1 = out + (size_t)BATCH * NPTS * KNN + (size_t)gid * KNN; // center
    #pragma unroll
    for (int j = 0; j < KNN; j++) {
        o0[j] = (float)mi[j];
        o1[j] = (float)n;
    }
}

// --------------------------------- launch ---------------------------------
extern "C" void kernel_launch(void* const* d_in, const int* in_sizes, int n_in,
                              void* d_out, int out_size) {
    const float* x  = nullptr;
    const float* y  = nullptr;
    const float* rp = nullptr;
    for (int i = 0; i < n_in; i++) {
        if (in_sizes[i] == RP_ELEMS && rp == nullptr) rp = (const float*)d_in[i];
        else if (x == nullptr) x = (const float*)d_in[i];
        else if (y == nullptr) y = (const float*)d_in[i];
    }
    if (!x || !y || !rp) return;
    float* out = (float*)d_out;

    dim3 g1(NPTS / 32, BATCH, 2), b1(32, 8);
    normalize_split<<<g1, b1>>>(x, y);

    dim3 g2(NTILES, NSPLIT, BATCH);
    knn_mma<<<g2, 128>>>(rp);

    knn_finalize<<<(BATCH * NPTS + 127) / 128, 128>>>(out);
}

// round 10
// speedup vs baseline: 1.1172x; 1.1172x over previous
#include <cuda_runtime.h>
#include <cuda_fp16.h>
#include <cstdint>

#define BATCH  4
#define CH     192
#define NPTS   3136
#define KNN    9
#define NSPLIT 3
#define NTILES 49            /* m-tiles / n-tiles of 64 */
#define RP_ELEMS (NPTS * NPTS)
#define POS_INF __int_as_float(0x7f800000)

#define NBLKS 196            /* NPTS/16  (A m16 blocks)  */
#define MBLKS 392            /* NPTS/8   (B n8  blocks)  */
#define KSTEPS 12            /* CH/16 */
#define INV_SCALE 4.8828125e-4f   /* 1/2048 */

// ---------------- scratch (device globals; no allocation allowed) ----------
// A fragments (f16): [b][nblk][ks][split][lane][reg(4)x2 halves]
__device__ __align__(16) __half g_xA[(size_t)BATCH * NBLKS * KSTEPS * 2 * 32 * 8];
// B fragments (f16): [b][mblk][ks][lane][word(4)=b0s0,b1s0,b0s1,b1s1][2 halves]
__device__ __align__(16) __half g_yB[(size_t)BATCH * MBLKS * KSTEPS * 32 * 8];
__device__ float g_xn2[BATCH * NPTS];
__device__ float g_yn2[BATCH * NPTS];
__device__ float g_pv[BATCH * NPTS * NSPLIT * KNN];
__device__ int   g_pi[BATCH * NPTS * NSPLIT * KNN];

__device__ __forceinline__ bool lex_less(float v, int i, float v2, int i2) {
    return (v < v2) || (v == v2 && i < i2);
}
#define TOPK_INSERT(v, idx, LV, LI)                                        \
  do {                                                                     \
    if (lex_less((v), (idx), LV[KNN-1], LI[KNN-1])) {                      \
      LV[KNN-1] = (v); LI[KNN-1] = (idx);                                  \
      _Pragma("unroll")                                                    \
      for (int _j = KNN-1; _j > 0; --_j) {                                 \
        if (lex_less(LV[_j], LI[_j], LV[_j-1], LI[_j-1])) {                \
          float _tv = LV[_j]; LV[_j] = LV[_j-1]; LV[_j-1] = _tv;           \
          int   _ti = LI[_j]; LI[_j] = LI[_j-1]; LI[_j-1] = _ti;           \
        }                                                                  \
      }                                                                    \
    }                                                                      \
  } while (0)

#define MMA_F16(d, a, bb0, bb1)                                            \
  asm volatile("mma.sync.aligned.m16n8k16.row.col.f32.f16.f16.f32 "        \
      "{%0,%1,%2,%3},{%4,%5,%6,%7},{%8,%9},{%0,%1,%2,%3};"                 \
      : "+f"((d)[0]), "+f"((d)[1]), "+f"((d)[2]), "+f"((d)[3])             \
      : "r"((a).x), "r"((a).y), "r"((a).z), "r"((a).w),                    \
        "r"(bb0), "r"(bb1))

#define CP_ASYNC_CG16(dst, src)                                            \
  asm volatile("cp.async.cg.shared.global [%0], [%1], 16;"                 \
               :: "r"(dst), "l"(src) : "memory")
#define CP_COMMIT() asm volatile("cp.async.commit_group;" ::: "memory")
#define CP_WAIT0()  asm volatile("cp.async.wait_group 0;" ::: "memory")

__device__ __forceinline__ uint32_t smem_to_u32(const void* p) {
    uint32_t a;
    asm("{ .reg .u64 t; cvta.to.shared.u64 t, %1; cvt.u32.u64 %0, t; }"
        : "=r"(a) : "l"(p));
    return a;
}

// ------ kernel 1: L2-normalize over C + scaled f16 split + frag scatter ----
__global__ void normalize_split(const float* __restrict__ xin,
                                const float* __restrict__ yin) {
    int sel = blockIdx.z;                     // 0: x -> gA, 1: y -> gB
    const float* src = sel ? yin : xin;
    float* s2o = sel ? g_yn2 : g_xn2;
    int b  = blockIdx.y;
    int n0 = blockIdx.x * 32;
    int tx = threadIdx.x, ty = threadIdx.y;   // 32 x 8
    int tid = ty * 32 + tx;

    __shared__ float tile[CH][33];
    __shared__ float red[8][33];
    __shared__ float dnm[32];

    const float* sb = src + (size_t)b * CH * NPTS + n0 + tx;
    float acc = 0.f;
    #pragma unroll
    for (int c = ty; c < CH; c += 8) {
        float v = sb[(size_t)c * NPTS];
        tile[c][tx] = v;
        acc += v * v;
    }
    red[ty][tx] = acc;
    __syncthreads();
    if (ty == 0) {
        float s = red[0][tx];
        #pragma unroll
        for (int j = 1; j < 8; j++) s += red[j][tx];
        dnm[tx] = fmaxf(sqrtf(s), 1e-12f);
    }
    __syncthreads();

    // write phase: thread -> (row r, 24-channel chunk)
    int r  = tid >> 3;
    int cb = (tid & 7) * 24;
    float dn = dnm[r];
    int n = n0 + r;
    float s2 = 0.f;
    #pragma unroll
    for (int k = 0; k < 24; k++) {
        int c = cb + k;
        float v = tile[c][r] / dn;
        s2 += v * v;
        __half h0 = __float2half_rn(v);
        __half h1 = __float2half_rn((v - __half2float(h0)) * 2048.0f);

        int ks = c >> 4, kk = c & 15;
        if (sel == 0) {
            int mm   = n & 15;
            int lane = ((mm & 7) << 2) | ((kk & 7) >> 1);
            int reg  = ((kk >> 3) << 1) | ((mm >> 3) & 1);
            size_t base = (((size_t)b * NBLKS + (n >> 4)) * KSTEPS + ks) * 2;
            size_t off  = reg * 2 + (kk & 1);
            g_xA[((base + 0) * 32 + lane) * 8 + off] = h0;
            g_xA[((base + 1) * 32 + lane) * 8 + off] = h1;
        } else {
            int lane = ((n & 7) << 2) | ((kk & 7) >> 1);
            int breg = kk >> 3;
            size_t base = ((((size_t)b * MBLKS + (n >> 3)) * KSTEPS + ks) * 32
                           + lane) * 8;
            g_yB[base + (0 * 2 + breg) * 2 + (kk & 1)] = h0;  // words 0,1: s0
            g_yB[base + (2 + breg) * 2 + (kk & 1)]     = h1;  // words 2,3: s1
        }
    }
    #pragma unroll
    for (int o = 4; o > 0; o >>= 1)
        s2 += __shfl_down_sync(0xffffffffu, s2, o, 8);
    if ((tid & 7) == 0) s2o[(size_t)b * NPTS + n] = s2;
}

// stage B fragments for (mt2, kc2) into smem at dst_u32 via cp.async
__device__ __forceinline__ void stage_b(int b, int mt2, int kc2,
                                        uint32_t dst_u32, int tid) {
    const uint4* src = ((const uint4*)g_yB)
        + ((size_t)b * MBLKS + mt2 * 8) * (KSTEPS * 32) + kc2 * 64;
    #pragma unroll
    for (int i = 0; i < 4; i++) {
        int f = tid + i * 128;
        CP_ASYNC_CG16(dst_u32 + (uint32_t)f * 16,
                      src + (f >> 6) * (KSTEPS * 32) + (f & 63));
    }
}

// ------ kernel 2: scaled-2-term f16 mma.sync GEMM + streaming top-9 --------
__global__ void __launch_bounds__(128, 4)
knn_mma(const float* __restrict__ rp) {
    __shared__ union {
        uint4 bstage[2][512];               // 2 x 8 KB B-fragment buffers
        struct { float cv[64 * 18]; int ci[64 * 18]; } c;
    } shr;
    __shared__ float ds[64 * 65];           // raw dot products
    __shared__ float x2s[64], y2sh[64];

    int b     = blockIdx.z;
    int split = blockIdx.y;
    int nt    = blockIdx.x;
    int n0    = nt * 64;

    int tid  = threadIdx.x;
    int lane = tid & 31;
    int wid  = tid >> 5;
    int wn   = wid & 1;          // n half (rows wn*32)
    int wm   = wid >> 1;         // m half (cols wm*32)
    int srow = tid & 63, half = tid >> 6;   // scan role

    uint32_t bst_u32 = smem_to_u32(&shr.bstage[0][0]);

    if (tid < 64) x2s[tid] = g_xn2[b * NPTS + n0 + tid];

    float bvK[KNN]; int biK[KNN];
    #pragma unroll
    for (int j = 0; j < KNN; j++) { bvK[j] = POS_INF; biK[j] = 0x7FFFFFFF; }

    int t_lo = (split == 0) ? 0  : (split == 1 ? 17 : 33);
    int t_hi = (split == 0) ? 17 : (split == 1 ? 33 : 49);

    const uint4* gA4 = (const uint4*)g_xA;
    size_t nb0 = (size_t)b * NBLKS + nt * 4 + wn * 2;   // warp's first nblk

    // prologue: stage (t_lo, kc=0) into buffer 0
    stage_b(b, t_lo, 0, bst_u32, tid);
    CP_COMMIT();

    int buf = 0;
    for (int mt = t_lo; mt < t_hi; mt++) {
        int m0 = mt * 64;
        if (tid < 64) y2sh[tid] = g_yn2[b * NPTS + m0 + tid];

        float acc0[2][4][4], accC[2][4][4];
        #pragma unroll
        for (int bi = 0; bi < 2; bi++)
            #pragma unroll
            for (int bj = 0; bj < 4; bj++)
                #pragma unroll
                for (int e = 0; e < 4; e++) {
                    acc0[bi][bj][e] = 0.f; accC[bi][bj][e] = 0.f;
                }

        CP_WAIT0();
        __syncthreads();   // staged buffer visible; prev scan done

        for (int kc = 0; kc < 6; kc++) {
            // issue next stage (next kc, or next m-tile's kc0)
            bool issued = true;
            if (kc < 5)               stage_b(b, mt, kc + 1, bst_u32 + (buf ^ 1) * 8192, tid);
            else if (mt + 1 < t_hi)   stage_b(b, mt + 1, 0, bst_u32 + (buf ^ 1) * 8192, tid);
            else issued = false;
            if (issued) CP_COMMIT();

            // compute on current buffer
            const uint4* bst = &shr.bstage[buf][0];
            #pragma unroll
            for (int kl = 0; kl < 2; kl++) {
                int ks = kc * 2 + kl;
                uint4 afr[2][2];
                #pragma unroll
                for (int bi = 0; bi < 2; bi++)
                    #pragma unroll
                    for (int s = 0; s < 2; s++)
                        afr[bi][s] = gA4[(((nb0 + bi) * KSTEPS + ks) * 2 + s) * 32 + lane];
                uint4 bf[4];
                #pragma unroll
                for (int bj = 0; bj < 4; bj++)
                    bf[bj] = bst[((wm * 4 + bj) * 2 + kl) * 32 + lane];
                // acc0 += x0*y0
                #pragma unroll
                for (int bi = 0; bi < 2; bi++)
                    #pragma unroll
                    for (int bj = 0; bj < 4; bj++)
                        MMA_F16(acc0[bi][bj], afr[bi][0], bf[bj].x, bf[bj].y);
                // accC += x0*y1s
                #pragma unroll
                for (int bi = 0; bi < 2; bi++)
                    #pragma unroll
                    for (int bj = 0; bj < 4; bj++)
                        MMA_F16(accC[bi][bj], afr[bi][0], bf[bj].z, bf[bj].w);
                // accC += x1s*y0
                #pragma unroll
                for (int bi = 0; bi < 2; bi++)
                    #pragma unroll
                    for (int bj = 0; bj < 4; bj++)
                        MMA_F16(accC[bi][bj], afr[bi][1], bf[bj].x, bf[bj].y);
            }

            if (kc < 5) { CP_WAIT0(); __syncthreads(); }
            buf ^= 1;
        }
        // NOTE: next-tile stage (if any) still in flight; waited at loop top.

        // epilogue: xy = acc0 + accC/2048; scatter scalars to ds
        #pragma unroll
        for (int bi = 0; bi < 2; bi++)
            #pragma unroll
            for (int bj = 0; bj < 4; bj++) {
                int r0 = wn * 32 + bi * 16 + (lane >> 2);
                int c0 = wm * 32 + bj * 8 + (lane & 3) * 2;
                ds[r0 * 65 + c0]           = acc0[bi][bj][0] + accC[bi][bj][0] * INV_SCALE;
                ds[r0 * 65 + c0 + 1]       = acc0[bi][bj][1] + accC[bi][bj][1] * INV_SCALE;
                ds[(r0 + 8) * 65 + c0]     = acc0[bi][bj][2] + accC[bi][bj][2] * INV_SCALE;
                ds[(r0 + 8) * 65 + c0 + 1] = acc0[bi][bj][3] + accC[bi][bj][3] * INV_SCALE;
            }
        __syncthreads();

        // scan: 2 threads per row, 32 cols each, streaming top-9
        {
            float x2v = x2s[srow];
            const float*  dsr = ds + srow * 65 + half * 32;
            const float4* rpr = (const float4*)(rp + (size_t)(n0 + srow) * NPTS
                                                + m0 + half * 32);
            #pragma unroll
            for (int c4 = 0; c4 < 8; c4++) {
                float4 rv = rpr[c4];
                float rr[4] = {rv.x, rv.y, rv.z, rv.w};
                #pragma unroll
                for (int e = 0; e < 4; e++) {
                    int c  = c4 * 4 + e;
                    float xy = dsr[c];
                    float d2 = x2v + y2sh[half * 32 + c] - 2.0f * xy;
                    float d  = sqrtf(fmaxf(d2, 0.0f)) + rr[e];
                    TOPK_INSERT(d, m0 + half * 32 + c, bvK, biK);
                }
            }
        }
        __syncthreads();   // scan done before smem reuse
    }

    // dump per-thread candidates (aliases dead B buffers) and merge halves
    #pragma unroll
    for (int j = 0; j < KNN; j++) {
        shr.c.cv[srow * 18 + half * 9 + j] = bvK[j];
        shr.c.ci[srow * 18 + half * 9 + j] = biK[j];
    }
    __syncthreads();
    if (tid < 64) {
        float mv[KNN]; int mi[KNN];
        #pragma unroll
        for (int j = 0; j < KNN; j++) { mv[j] = POS_INF; mi[j] = 0x7FFFFFFF; }
        #pragma unroll
        for (int t = 0; t < 18; t++) {
            float v = shr.c.cv[tid * 18 + t]; int ii = shr.c.ci[tid * 18 + t];
            TOPK_INSERT(v, ii, mv, mi);
        }
        size_t base = ((size_t)(b * NPTS + n0 + tid) * NSPLIT + split) * KNN;
        #pragma unroll
        for (int j = 0; j < KNN; j++) { g_pv[base + j] = mv[j]; g_pi[base + j] = mi[j]; }
    }
}

// --------- kernel 3: merge splits, emit (2,B,N,K) as FLOAT32 --------------
__global__ void knn_finalize(float* __restrict__ out) {
    int gid = blockIdx.x * blockDim.x + threadIdx.x;  // b*NPTS + n
    if (gid >= BATCH * NPTS) return;
    float mv[KNN]; int mi[KNN];
    #pragma unroll
    for (int j = 0; j < KNN; j++) { mv[j] = POS_INF; mi[j] = 0x7FFFFFFF; }
    size_t base = (size_t)gid * NSPLIT * KNN;
    for (int t = 0; t < NSPLIT * KNN; t++) {
        float v = g_pv[base + t]; int ii = g_pi[base + t];
        TOPK_INSERT(v, ii, mv, mi);
    }
    int n = gid % NPTS;
    float* o0 = out + (size_t)gid * KNN;                              // nn_idx
    float* o1 = out + (size_t)BATCH * NPTS * KNN + (size_t)gid * KNN; // center
    #pragma unroll
    for (int j = 0; j < KNN; j++) {
        o0[j] = (float)mi[j];
        o1[j] = (float)n;
    }
}

// --------------------------------- launch ---------------------------------
extern "C" void kernel_launch(void* const* d_in, const int* in_sizes, int n_in,
                              void* d_out, int out_size) {
    const float* x  = nullptr;
    const float* y  = nullptr;
    const float* rp = nullptr;
    for (int i = 0; i < n_in; i++) {
        if (in_sizes[i] == RP_ELEMS && rp == nullptr) rp = (const float*)d_in[i];
        else if (x == nullptr) x = (const float*)d_in[i];
        else if (y == nullptr) y = (const float*)d_in[i];
    }
    if (!x || !y || !rp) return;
    float* out = (float*)d_out;

    dim3 g1(NPTS / 32, BATCH, 2), b1(32, 8);
    normalize_split<<<g1, b1>>>(x, y);

    dim3 g2(NTILES, NSPLIT, BATCH);
    knn_mma<<<g2, 128>>>(rp);

    knn_finalize<<<(BATCH * NPTS + 127) / 128, 128>>>(out);
}